// round 1
// baseline (speedup 1.0000x reference)
#include <cuda_runtime.h>
#include <math.h>

// ---------------- problem constants ----------------
#define B_      2
#define L_      2048
#define DM      1024          // d_model
#define DI      2048          // d_inner
#define NH      32            // nheads
#define HD      64            // headdim
#define DS      64            // d_state
#define CONVD   2176          // d_inner + 2*d_state
#define DPROJ   4256          // 2*d_inner + 2*d_state + nheads
#define TT      (B_*L_)       // 4096 tokens
#define EPS_    1e-5f

// ---------------- scratch (device globals; no allocation allowed) ----------------
__device__ float g_h1 [TT*DM];       // ln1 output
__device__ float g_zx [TT*DPROJ];    // in_proj output (z | xBC_raw | dt_raw)
__device__ float g_xbc[TT*CONVD];    // silu(conv) output
__device__ float g_dt [TT*NH];       // softplus dt
__device__ float g_y  [TT*DI];       // scan output (+ D*x)
__device__ float g_yn [TT*DI];       // gated rmsnorm output
__device__ float g_x2 [TT*DM];       // residual after mamba
__device__ float g_h2 [TT*DM];       // ln2 output
__device__ float g_gl [TT*4*DM];     // gelu(mlp1) output

// ---------------- helpers ----------------
__device__ __forceinline__ float block_reduce_256(float v) {
    static __shared__ float sh[8];
    int tid = threadIdx.x;
    #pragma unroll
    for (int o = 16; o > 0; o >>= 1) v += __shfl_xor_sync(0xffffffffu, v, o);
    __syncthreads();                 // protect sh from previous call
    if ((tid & 31) == 0) sh[tid >> 5] = v;
    __syncthreads();
    return sh[0]+sh[1]+sh[2]+sh[3]+sh[4]+sh[5]+sh[6]+sh[7];
}

__device__ __forceinline__ float silu_f(float x) {
    return x / (1.f + __expf(-x));
}

// ---------------- LayerNorm (rows of 1024) ----------------
__global__ void ln_kernel(const float* __restrict__ in, const float* __restrict__ w,
                          const float* __restrict__ b, float* __restrict__ out) {
    int row = blockIdx.x, tid = threadIdx.x;
    float4 v = ((const float4*)(in + (size_t)row * DM))[tid];
    float s  = v.x + v.y + v.z + v.w;
    float sq = v.x*v.x + v.y*v.y + v.z*v.z + v.w*v.w;
    float tot   = block_reduce_256(s);
    float totsq = block_reduce_256(sq);
    float mean = tot * (1.f / DM);
    float var  = totsq * (1.f / DM) - mean * mean;
    float inv  = rsqrtf(var + EPS_);
    float4 wv = ((const float4*)w)[tid];
    float4 bv = ((const float4*)b)[tid];
    float4 o;
    o.x = (v.x - mean) * inv * wv.x + bv.x;
    o.y = (v.y - mean) * inv * wv.y + bv.y;
    o.z = (v.z - mean) * inv * wv.z + bv.z;
    o.w = (v.w - mean) * inv * wv.w + bv.w;
    ((float4*)(out + (size_t)row * DM))[tid] = o;
}

// ---------------- SGEMM: C[M,N] = A[M,K] @ B[N,K]^T  (+ epilogue) ----------------
// EPI: 0 = none, 1 = +res, 2 = +bias then exact gelu, 3 = +bias +res
#define BM 128
#define BN 128
#define BK 16
template<int EPI>
__global__ void __launch_bounds__(256)
sgemm_nt(const float* __restrict__ A, const float* __restrict__ Bm,
         const float* __restrict__ bias, const float* __restrict__ res,
         float* __restrict__ C, int M, int N, int K) {
    __shared__ float As[BK][BM + 4];
    __shared__ float Bs[BK][BN + 4];
    int tid = threadIdx.x;
    int bx = blockIdx.x, by = blockIdx.y;
    int ty = tid >> 4, tx = tid & 15;       // 16x16 thread tile, 8x8 each
    int lr = tid >> 2, lc = tid & 3;        // load mapping

    float acc[8][8];
    #pragma unroll
    for (int i = 0; i < 8; i++)
        #pragma unroll
        for (int j = 0; j < 8; j++) acc[i][j] = 0.f;

    for (int k0 = 0; k0 < K; k0 += BK) {
        #pragma unroll
        for (int s = 0; s < 2; s++) {
            int r = lr + s * 64;
            const float* ap = A + (size_t)(by * BM + r) * K + k0 + lc * 4;
            float4 v = *(const float4*)ap;
            As[lc*4+0][r] = v.x; As[lc*4+1][r] = v.y;
            As[lc*4+2][r] = v.z; As[lc*4+3][r] = v.w;
        }
        #pragma unroll
        for (int s = 0; s < 2; s++) {
            int n  = lr + s * 64;
            int gn = bx * BN + n;
            float4 v = make_float4(0.f, 0.f, 0.f, 0.f);
            if (gn < N) v = *(const float4*)(Bm + (size_t)gn * K + k0 + lc * 4);
            Bs[lc*4+0][n] = v.x; Bs[lc*4+1][n] = v.y;
            Bs[lc*4+2][n] = v.z; Bs[lc*4+3][n] = v.w;
        }
        __syncthreads();
        #pragma unroll
        for (int kk = 0; kk < BK; kk++) {
            float4 a0 = *(const float4*)&As[kk][ty * 8];
            float4 a1 = *(const float4*)&As[kk][ty * 8 + 4];
            float4 b0 = *(const float4*)&Bs[kk][tx * 8];
            float4 b1 = *(const float4*)&Bs[kk][tx * 8 + 4];
            float ra[8] = {a0.x,a0.y,a0.z,a0.w,a1.x,a1.y,a1.z,a1.w};
            float rb[8] = {b0.x,b0.y,b0.z,b0.w,b1.x,b1.y,b1.z,b1.w};
            #pragma unroll
            for (int i = 0; i < 8; i++)
                #pragma unroll
                for (int j = 0; j < 8; j++) acc[i][j] += ra[i] * rb[j];
        }
        __syncthreads();
    }

    int gcb = bx * BN + tx * 8;
    if (gcb >= N) return;        // N % 8 == 0, so whole 8-col group valid or not
    #pragma unroll
    for (int i = 0; i < 8; i++) {
        int gr = by * BM + ty * 8 + i;
        #pragma unroll
        for (int j = 0; j < 8; j++) {
            int gc = gcb + j;
            float v = acc[i][j];
            if (EPI == 1) v += res[(size_t)gr * N + gc];
            if (EPI == 2) {
                v += bias[gc];
                v = 0.5f * v * (1.f + erff(v * 0.70710678118654752f));
            }
            if (EPI == 3) v += bias[gc] + res[(size_t)gr * N + gc];
            C[(size_t)gr * N + gc] = v;
        }
    }
}

// ---------------- causal depthwise conv(4) + silu ----------------
__global__ void conv_kernel(const float* __restrict__ zx, const float* __restrict__ w,
                            const float* __restrict__ bias, float* __restrict__ out) {
    int idx = blockIdx.x * blockDim.x + threadIdx.x;
    if (idx >= TT * CONVD) return;
    int c = idx % CONVD;
    int t = idx / CONVD;       // b*L + l
    int l = t % L_;
    float acc = bias[c];
    #pragma unroll
    for (int k = 0; k < 4; k++) {
        int ls = l - 3 + k;
        if (ls >= 0)
            acc += zx[(size_t)(t - 3 + k) * DPROJ + DI + c] * w[c * 4 + k];
    }
    out[idx] = silu_f(acc);
}

// ---------------- dt = softplus(raw + bias) ----------------
__global__ void dt_kernel(const float* __restrict__ zx, const float* __restrict__ dtb,
                          float* __restrict__ dt) {
    int idx = blockIdx.x * blockDim.x + threadIdx.x;
    if (idx >= TT * NH) return;
    int h = idx % NH;
    float v = zx[(size_t)(idx / NH) * DPROJ + DI + CONVD + h] + dtb[h];
    dt[idx] = (v > 20.f) ? v : log1pf(expf(v));
}

// ---------------- selective scan: 128 CTAs = (b,h,half-of-P), 128 threads ----------------
#define CH 8
__global__ void __launch_bounds__(128)
scan_kernel(const float* __restrict__ xbc, const float* __restrict__ dtg,
            const float* __restrict__ A_log, const float* __restrict__ Dp,
            float* __restrict__ y) {
    int blk  = blockIdx.x;
    int half = blk & 1;
    int bh   = blk >> 1;
    int b = bh / NH, h = bh % NH;
    int tid = threadIdx.x;
    int pl  = tid >> 2;          // 0..31  (local p)
    int q   = tid & 3;           // n-quarter
    int p   = half * 32 + pl;

    float Aneg = -expf(A_log[h]);
    float Dh   = Dp[h];

    __shared__ float sB[CH][DS], sC[CH][DS], sx[CH][32], sdt[CH];

    float hreg[16];
    #pragma unroll
    for (int i = 0; i < 16; i++) hreg[i] = 0.f;

    const float* base = xbc + (size_t)b * L_ * CONVD;

    for (int t0 = 0; t0 < L_; t0 += CH) {
        #pragma unroll
        for (int tt = 0; tt < CH; tt++) {
            int t = t0 + tt;
            const float* rowp = base + (size_t)t * CONVD;
            if (tid < 64) sB[tt][tid]      = rowp[DI + tid];
            else          sC[tt][tid - 64] = rowp[DI + DS + (tid - 64)];
        }
        #pragma unroll
        for (int tt = 0; tt < CH; tt++) {
            int t = t0 + tt;
            if (tid < 32)       sx[tt][tid] = base[(size_t)t * CONVD + h * HD + half * 32 + tid];
            else if (tid == 32) sdt[tt]     = dtg[((size_t)b * L_ + t) * NH + h];
        }
        __syncthreads();

        #pragma unroll
        for (int tt = 0; tt < CH; tt++) {
            float dtv = sdt[tt];
            float dA  = expf(dtv * Aneg);
            float xv  = sx[tt][pl];
            float cb  = dtv * xv;
            float acc = 0.f;
            #pragma unroll
            for (int i = 0; i < 16; i++) {
                int n = q * 16 + i;
                float hv = hreg[i] * dA + cb * sB[tt][n];
                hreg[i] = hv;
                acc += hv * sC[tt][n];
            }
            acc += __shfl_xor_sync(0xffffffffu, acc, 1);
            acc += __shfl_xor_sync(0xffffffffu, acc, 2);
            if (q == 0) {
                int t = t0 + tt;
                y[((size_t)b * L_ + t) * DI + h * HD + p] = acc + Dh * xv;
            }
        }
        __syncthreads();
    }
}

// ---------------- gated RMSNorm: y * silu(z), rms over 2048, * norm_w ----------------
__global__ void rmsnorm_kernel(const float* __restrict__ y, const float* __restrict__ zx,
                               const float* __restrict__ nw, float* __restrict__ out) {
    int row = blockIdx.x, tid = threadIdx.x;
    const float* yr = y  + (size_t)row * DI;
    const float* zr = zx + (size_t)row * DPROJ;   // z = first DI channels
    float vals[8];
    float sq = 0.f;
    #pragma unroll
    for (int i = 0; i < 8; i++) {
        int c = tid + i * 256;
        float z = zr[c];
        float v = yr[c] * silu_f(z);
        vals[i] = v;
        sq += v * v;
    }
    float tot = block_reduce_256(sq);
    float scale = rsqrtf(tot * (1.f / DI) + EPS_);
    #pragma unroll
    for (int i = 0; i < 8; i++) {
        int c = tid + i * 256;
        out[(size_t)row * DI + c] = vals[i] * scale * nw[c];
    }
}

// ---------------- launch ----------------
extern "C" void kernel_launch(void* const* d_in, const int* in_sizes, int n_in,
                              void* d_out, int out_size) {
    const float* x          = (const float*)d_in[0];
    const float* ln1_w      = (const float*)d_in[1];
    const float* ln1_b      = (const float*)d_in[2];
    const float* in_proj_w  = (const float*)d_in[3];
    const float* conv_w     = (const float*)d_in[4];
    const float* conv_b     = (const float*)d_in[5];
    const float* dt_bias    = (const float*)d_in[6];
    const float* A_log      = (const float*)d_in[7];
    const float* Dv         = (const float*)d_in[8];
    const float* norm_w     = (const float*)d_in[9];
    const float* out_proj_w = (const float*)d_in[10];
    const float* ln2_w      = (const float*)d_in[11];
    const float* ln2_b      = (const float*)d_in[12];
    const float* mlp_w1     = (const float*)d_in[13];
    const float* mlp_b1     = (const float*)d_in[14];
    const float* mlp_w2     = (const float*)d_in[15];
    const float* mlp_b2     = (const float*)d_in[16];
    float* out = (float*)d_out;

    static float *p_h1=nullptr,*p_zx,*p_xbc,*p_dt,*p_y,*p_yn,*p_x2,*p_h2,*p_gl;
    if (!p_h1) {
        cudaGetSymbolAddress((void**)&p_h1,  g_h1);
        cudaGetSymbolAddress((void**)&p_zx,  g_zx);
        cudaGetSymbolAddress((void**)&p_xbc, g_xbc);
        cudaGetSymbolAddress((void**)&p_dt,  g_dt);
        cudaGetSymbolAddress((void**)&p_y,   g_y);
        cudaGetSymbolAddress((void**)&p_yn,  g_yn);
        cudaGetSymbolAddress((void**)&p_x2,  g_x2);
        cudaGetSymbolAddress((void**)&p_h2,  g_h2);
        cudaGetSymbolAddress((void**)&p_gl,  g_gl);
    }

    // 1) LN1
    ln_kernel<<<TT, 256>>>(x, ln1_w, ln1_b, p_h1);

    // 2) in_proj: (4096 x 1024) @ (4256 x 1024)^T
    {
        dim3 g((DPROJ + BN - 1) / BN, TT / BM);
        sgemm_nt<0><<<g, 256>>>(p_h1, in_proj_w, nullptr, nullptr, p_zx, TT, DPROJ, DM);
    }

    // 3) conv + silu; dt softplus
    conv_kernel<<<(TT * CONVD + 255) / 256, 256>>>(p_zx, conv_w, conv_b, p_xbc);
    dt_kernel<<<(TT * NH + 255) / 256, 256>>>(p_zx, dt_bias, p_dt);

    // 4) selective scan
    scan_kernel<<<B_ * NH * 2, 128>>>(p_xbc, p_dt, A_log, Dv, p_y);

    // 5) gated rmsnorm
    rmsnorm_kernel<<<TT, 256>>>(p_y, p_zx, norm_w, p_yn);

    // 6) out_proj + residual: (4096 x 2048) @ (1024 x 2048)^T + x
    {
        dim3 g(DM / BN, TT / BM);
        sgemm_nt<1><<<g, 256>>>(p_yn, out_proj_w, nullptr, x, p_x2, TT, DM, DI);
    }

    // 7) LN2
    ln_kernel<<<TT, 256>>>(p_x2, ln2_w, ln2_b, p_h2);

    // 8) mlp1 + bias + gelu: (4096 x 1024) @ (4096 x 1024)^T
    {
        dim3 g(4 * DM / BN, TT / BM);
        sgemm_nt<2><<<g, 256>>>(p_h2, mlp_w1, mlp_b1, nullptr, p_gl, TT, 4 * DM, DM);
    }

    // 9) mlp2 + bias + residual -> out: (4096 x 4096) @ (1024 x 4096)^T
    {
        dim3 g(DM / BN, TT / BM);
        sgemm_nt<3><<<g, 256>>>(p_gl, mlp_w2, mlp_b2, p_x2, out, TT, DM, 4 * DM);
    }
}

// round 7
// speedup vs baseline: 1.5399x; 1.5399x over previous
#include <cuda_runtime.h>
#include <cuda_bf16.h>
#include <stdint.h>
#include <math.h>

typedef unsigned int       u32;
typedef unsigned long long u64;

// ---------------- problem constants ----------------
#define B_      2
#define L_      2048
#define DM      1024
#define DI      2048
#define NH      32
#define HD      64
#define DS      64
#define CONVD   2176
#define DPROJ   4256
#define TT      (B_*L_)
#define EPS_    1e-5f

// ---------------- scratch ----------------
__device__ float g_h1 [TT*DM];
__device__ float g_zx [TT*DPROJ];
__device__ float g_xbc[TT*CONVD];
__device__ float g_dt [TT*NH];
__device__ float g_y  [TT*DI];
__device__ float g_yn [TT*DI];
__device__ float g_x2 [TT*DM];
__device__ float g_h2 [TT*DM];
__device__ float g_gl [TT*4*DM];

// ---------------- helpers ----------------
__device__ __forceinline__ float block_reduce_256(float v) {
    static __shared__ float sh[8];
    int tid = threadIdx.x;
    #pragma unroll
    for (int o = 16; o > 0; o >>= 1) v += __shfl_xor_sync(0xffffffffu, v, o);
    __syncthreads();
    if ((tid & 31) == 0) sh[tid >> 5] = v;
    __syncthreads();
    return sh[0]+sh[1]+sh[2]+sh[3]+sh[4]+sh[5]+sh[6]+sh[7];
}

__device__ __forceinline__ float silu_f(float x) {
    return x / (1.f + __expf(-x));
}

__device__ __forceinline__ u32 smem_u32(const void* p) {
    u32 a;
    asm("{ .reg .u64 t; cvta.to.shared.u64 t, %1; cvt.u32.u64 %0, t; }" : "=r"(a) : "l"(p));
    return a;
}

__device__ __forceinline__ void ldsm_x4(u32& r0, u32& r1, u32& r2, u32& r3, u32 addr) {
    asm volatile("ldmatrix.sync.aligned.m8n8.x4.shared.b16 {%0,%1,%2,%3}, [%4];"
                 : "=r"(r0), "=r"(r1), "=r"(r2), "=r"(r3) : "r"(addr));
}

__device__ __forceinline__ void mma_bf16(float* d, u32 a0, u32 a1, u32 a2, u32 a3,
                                         u32 b0, u32 b1) {
    asm volatile(
        "mma.sync.aligned.m16n8k16.row.col.f32.bf16.bf16.f32 "
        "{%0,%1,%2,%3}, {%4,%5,%6,%7}, {%8,%9}, {%0,%1,%2,%3};"
        : "+f"(d[0]), "+f"(d[1]), "+f"(d[2]), "+f"(d[3])
        : "r"(a0), "r"(a1), "r"(a2), "r"(a3), "r"(b0), "r"(b1));
}

__device__ __forceinline__ void split2(float x, float y, u32& hi, u32& lo) {
    __nv_bfloat16 hx = __float2bfloat16(x);
    __nv_bfloat16 hy = __float2bfloat16(y);
    float rx = x - __bfloat162float(hx);
    float ry = y - __bfloat162float(hy);
    __nv_bfloat16 lx = __float2bfloat16(rx);
    __nv_bfloat16 ly = __float2bfloat16(ry);
    hi = (u32)__bfloat16_as_ushort(hx) | ((u32)__bfloat16_as_ushort(hy) << 16);
    lo = (u32)__bfloat16_as_ushort(lx) | ((u32)__bfloat16_as_ushort(ly) << 16);
}

// ---------------- split-bf16 HMMA GEMM: C[M,N] = A[M,K] @ B[N,K]^T ----------------
// epi: 0 none, 1 +res, 2 +bias+gelu, 3 +bias+res
// CTA 128x128, BK=32 fp32. smem rows padded to 80B. Double-buffered.
#define ROWB   80            /* bytes per padded smem row (32 bf16 -> 40) */
#define BUF_A_LO 10240u
#define BUF_B_HI 20480u
#define BUF_B_LO 30720u
#define STAGE_SZ 40960u
#define SMEM_MM (2u * STAGE_SZ)   /* 81920 */

__global__ void __launch_bounds__(256)
mm_kernel(const float* __restrict__ A, const float* __restrict__ Bm,
          const float* __restrict__ bias, const float* __restrict__ res,
          float* __restrict__ C, int M, int N, int K, int epi) {
    extern __shared__ char smc[];
    u32 sb = smem_u32(smc);

    int tid = threadIdx.x;
    int wid = tid >> 5, t = tid & 31;
    int bx = blockIdx.x, by = blockIdx.y;
    int wm = wid >> 2, wn = wid & 3;          // warp tile: m64 x n32

    // gmem load mapping: pass p(0..7): p<4 -> A rows p*32+(tid>>3); else B.
    int lrow = tid >> 3;          // 0..31
    int lq   = tid & 7;           // float4 index within 32-float slice

    float4 rg[8];
    float acc[4][4][4];
    #pragma unroll
    for (int i = 0; i < 4; i++)
        #pragma unroll
        for (int j = 0; j < 4; j++)
            #pragma unroll
            for (int k = 0; k < 4; k++) acc[i][j][k] = 0.f;

    const int nc = K >> 5;

    // ---- load k-slice c into rg ----
    auto load_regs = [&](int c) {
        #pragma unroll
        for (int p = 0; p < 4; p++) {
            int gr = by * 128 + p * 32 + lrow;
            rg[p] = *(const float4*)(A + (size_t)gr * K + (c << 5) + lq * 4);
        }
        #pragma unroll
        for (int p = 0; p < 4; p++) {
            int gn = bx * 128 + p * 32 + lrow;
            rg[4 + p] = (gn < N)
                ? *(const float4*)(Bm + (size_t)gn * K + (c << 5) + lq * 4)
                : make_float4(0.f, 0.f, 0.f, 0.f);
        }
    };

    // ---- convert + store rg into smem stage s ----
    auto store_smem = [&](int s) {
        u32 base = sb + (u32)s * STAGE_SZ;
        #pragma unroll
        for (int p = 0; p < 8; p++) {
            u32 off = (p < 4 ? 0u : BUF_B_HI) + (u32)((p & 3) * 32 + lrow) * ROWB + (u32)lq * 8;
            u32 h0, l0, h1, l1;
            split2(rg[p].x, rg[p].y, h0, l0);
            split2(rg[p].z, rg[p].w, h1, l1);
            u32 ahi = base + off, alo = ahi + BUF_A_LO;
            asm volatile("st.shared.v2.b32 [%0], {%1,%2};" :: "r"(ahi), "r"(h0), "r"(h1) : "memory");
            asm volatile("st.shared.v2.b32 [%0], {%1,%2};" :: "r"(alo), "r"(l0), "r"(l1) : "memory");
        }
    };

    // ldmatrix base offsets (within a stage)
    u32 arow = (u32)(wm * 64 + (t & 15));
    u32 acol = (u32)((t >> 4) << 4);                  // 0 or 16 bytes
    u32 brow = (u32)(wn * 32 + (t & 7) + ((t >> 4) << 3));
    u32 bcol = (u32)(((t >> 3) & 1) << 4);            // 0 or 16 bytes

    auto compute = [&](int s) {
        u32 base = sb + (u32)s * STAGE_SZ;
        #pragma unroll
        for (int ks = 0; ks < 2; ks++) {
            u32 kb = (u32)(ks * 32);
            u32 ah[4][4], al[4][4], bh[2][4], bl[2][4];
            #pragma unroll
            for (int mi = 0; mi < 4; mi++) {
                u32 ad = base + (arow + mi * 16) * ROWB + kb + acol;
                ldsm_x4(ah[mi][0], ah[mi][1], ah[mi][2], ah[mi][3], ad);
                ldsm_x4(al[mi][0], al[mi][1], al[mi][2], al[mi][3], ad + BUF_A_LO);
            }
            #pragma unroll
            for (int nj = 0; nj < 2; nj++) {
                u32 bd = base + BUF_B_HI + (brow + nj * 16) * ROWB + kb + bcol;
                ldsm_x4(bh[nj][0], bh[nj][1], bh[nj][2], bh[nj][3], bd);
                ldsm_x4(bl[nj][0], bl[nj][1], bl[nj][2], bl[nj][3], bd + BUF_A_LO);
            }
            #pragma unroll
            for (int mi = 0; mi < 4; mi++) {
                #pragma unroll
                for (int nj = 0; nj < 4; nj++) {
                    u32 b0h = bh[nj >> 1][(nj & 1) * 2], b1h = bh[nj >> 1][(nj & 1) * 2 + 1];
                    u32 b0l = bl[nj >> 1][(nj & 1) * 2], b1l = bl[nj >> 1][(nj & 1) * 2 + 1];
                    mma_bf16(acc[mi][nj], ah[mi][0], ah[mi][1], ah[mi][2], ah[mi][3], b0h, b1h);
                    mma_bf16(acc[mi][nj], ah[mi][0], ah[mi][1], ah[mi][2], ah[mi][3], b0l, b1l);
                    mma_bf16(acc[mi][nj], al[mi][0], al[mi][1], al[mi][2], al[mi][3], b0h, b1h);
                }
            }
        }
    };

    // ---- pipeline ----
    load_regs(0);
    store_smem(0);
    __syncthreads();
    for (int c = 0; c < nc; c++) {
        if (c + 1 < nc) load_regs(c + 1);
        compute(c & 1);
        if (c + 1 < nc) {
            __syncthreads();
            store_smem((c + 1) & 1);
            __syncthreads();
        }
    }

    // ---- epilogue ----
    int gid = t >> 2, tig = t & 3;
    #pragma unroll
    for (int mi = 0; mi < 4; mi++) {
        int gm0 = by * 128 + wm * 64 + mi * 16 + gid;
        #pragma unroll
        for (int nj = 0; nj < 4; nj++) {
            int gn = bx * 128 + wn * 32 + nj * 8 + tig * 2;
            if (gn >= N) continue;
            #pragma unroll
            for (int h = 0; h < 2; h++) {
                int gr = gm0 + h * 8;
                float vx = acc[mi][nj][h * 2 + 0];
                float vy = acc[mi][nj][h * 2 + 1];
                if (epi == 2 || epi == 3) {
                    float2 bv = *(const float2*)(bias + gn);
                    vx += bv.x; vy += bv.y;
                }
                if (epi == 2) {
                    vx = 0.5f * vx * (1.f + erff(vx * 0.70710678118654752f));
                    vy = 0.5f * vy * (1.f + erff(vy * 0.70710678118654752f));
                }
                if (epi == 1 || epi == 3) {
                    float2 rv = *(const float2*)(res + (size_t)gr * N + gn);
                    vx += rv.x; vy += rv.y;
                }
                float2 o; o.x = vx; o.y = vy;
                *(float2*)(C + (size_t)gr * N + gn) = o;
            }
        }
    }
}

// ---------------- LayerNorm ----------------
__global__ void ln_kernel(const float* __restrict__ in, const float* __restrict__ w,
                          const float* __restrict__ b, float* __restrict__ out) {
    int row = blockIdx.x, tid = threadIdx.x;
    float4 v = ((const float4*)(in + (size_t)row * DM))[tid];
    float s  = v.x + v.y + v.z + v.w;
    float sq = v.x*v.x + v.y*v.y + v.z*v.z + v.w*v.w;
    float tot   = block_reduce_256(s);
    float totsq = block_reduce_256(sq);
    float mean = tot * (1.f / DM);
    float var  = totsq * (1.f / DM) - mean * mean;
    float inv  = rsqrtf(var + EPS_);
    float4 wv = ((const float4*)w)[tid];
    float4 bv = ((const float4*)b)[tid];
    float4 o;
    o.x = (v.x - mean) * inv * wv.x + bv.x;
    o.y = (v.y - mean) * inv * wv.y + bv.y;
    o.z = (v.z - mean) * inv * wv.z + bv.z;
    o.w = (v.w - mean) * inv * wv.w + bv.w;
    ((float4*)(out + (size_t)row * DM))[tid] = o;
}

// ---------------- conv4 + silu ----------------
__global__ void conv_kernel(const float* __restrict__ zx, const float* __restrict__ w,
                            const float* __restrict__ bias, float* __restrict__ out) {
    int idx = blockIdx.x * blockDim.x + threadIdx.x;
    if (idx >= TT * CONVD) return;
    int c = idx % CONVD;
    int tt = idx / CONVD;
    int l = tt % L_;
    float acc = bias[c];
    #pragma unroll
    for (int k = 0; k < 4; k++) {
        int ls = l - 3 + k;
        if (ls >= 0)
            acc += zx[(size_t)(tt - 3 + k) * DPROJ + DI + c] * w[c * 4 + k];
    }
    out[idx] = silu_f(acc);
}

// ---------------- dt softplus ----------------
__global__ void dt_kernel(const float* __restrict__ zx, const float* __restrict__ dtb,
                          float* __restrict__ dt) {
    int idx = blockIdx.x * blockDim.x + threadIdx.x;
    if (idx >= TT * NH) return;
    int h = idx % NH;
    float v = zx[(size_t)(idx / NH) * DPROJ + DI + CONVD + h] + dtb[h];
    dt[idx] = (v > 20.f) ? v : log1pf(expf(v));
}

// ---------------- selective scan ----------------
#define CH 8
__global__ void __launch_bounds__(128)
scan_kernel(const float* __restrict__ xbc, const float* __restrict__ dtg,
            const float* __restrict__ A_log, const float* __restrict__ Dp,
            float* __restrict__ y) {
    int blk  = blockIdx.x;
    int half = blk & 1;
    int bh   = blk >> 1;
    int b = bh / NH, h = bh % NH;
    int tid = threadIdx.x;
    int pl  = tid >> 2;
    int q   = tid & 3;
    int p   = half * 32 + pl;

    float Aneg = -expf(A_log[h]);
    float Dh   = Dp[h];

    __shared__ float sB[CH][DS], sC[CH][DS], sx[CH][32], sdt[CH];

    float hreg[16];
    #pragma unroll
    for (int i = 0; i < 16; i++) hreg[i] = 0.f;

    const float* base = xbc + (size_t)b * L_ * CONVD;

    for (int t0 = 0; t0 < L_; t0 += CH) {
        #pragma unroll
        for (int tt = 0; tt < CH; tt++) {
            int tq = t0 + tt;
            const float* rowp = base + (size_t)tq * CONVD;
            if (tid < 64) sB[tt][tid]      = rowp[DI + tid];
            else          sC[tt][tid - 64] = rowp[DI + DS + (tid - 64)];
        }
        #pragma unroll
        for (int tt = 0; tt < CH; tt++) {
            int tq = t0 + tt;
            if (tid < 32)       sx[tt][tid] = base[(size_t)tq * CONVD + h * HD + half * 32 + tid];
            else if (tid == 32) sdt[tt]     = dtg[((size_t)b * L_ + tq) * NH + h];
        }
        __syncthreads();

        #pragma unroll
        for (int tt = 0; tt < CH; tt++) {
            float dtv = sdt[tt];
            float dA  = expf(dtv * Aneg);
            float xv  = sx[tt][pl];
            float cb  = dtv * xv;
            float acc = 0.f;
            #pragma unroll
            for (int i = 0; i < 16; i++) {
                int n = q * 16 + i;
                float hv = hreg[i] * dA + cb * sB[tt][n];
                hreg[i] = hv;
                acc += hv * sC[tt][n];
            }
            acc += __shfl_xor_sync(0xffffffffu, acc, 1);
            acc += __shfl_xor_sync(0xffffffffu, acc, 2);
            if (q == 0) {
                int tq = t0 + tt;
                y[((size_t)b * L_ + tq) * DI + h * HD + p] = acc + Dh * xv;
            }
        }
        __syncthreads();
    }
}

// ---------------- gated RMSNorm ----------------
__global__ void rmsnorm_kernel(const float* __restrict__ y, const float* __restrict__ zx,
                               const float* __restrict__ nw, float* __restrict__ out) {
    int row = blockIdx.x, tid = threadIdx.x;
    const float* yr = y  + (size_t)row * DI;
    const float* zr = zx + (size_t)row * DPROJ;
    float vals[8];
    float sq = 0.f;
    #pragma unroll
    for (int i = 0; i < 8; i++) {
        int c = tid + i * 256;
        float z = zr[c];
        float v = yr[c] * silu_f(z);
        vals[i] = v;
        sq += v * v;
    }
    float tot = block_reduce_256(sq);
    float scale = rsqrtf(tot * (1.f / DI) + EPS_);
    #pragma unroll
    for (int i = 0; i < 8; i++) {
        int c = tid + i * 256;
        out[(size_t)row * DI + c] = vals[i] * scale * nw[c];
    }
}

// ---------------- launch ----------------
extern "C" void kernel_launch(void* const* d_in, const int* in_sizes, int n_in,
                              void* d_out, int out_size) {
    const float* x          = (const float*)d_in[0];
    const float* ln1_w      = (const float*)d_in[1];
    const float* ln1_b      = (const float*)d_in[2];
    const float* in_proj_w  = (const float*)d_in[3];
    const float* conv_w     = (const float*)d_in[4];
    const float* conv_b     = (const float*)d_in[5];
    const float* dt_bias    = (const float*)d_in[6];
    const float* A_log      = (const float*)d_in[7];
    const float* Dv         = (const float*)d_in[8];
    const float* norm_w     = (const float*)d_in[9];
    const float* out_proj_w = (const float*)d_in[10];
    const float* ln2_w      = (const float*)d_in[11];
    const float* ln2_b      = (const float*)d_in[12];
    const float* mlp_w1     = (const float*)d_in[13];
    const float* mlp_b1     = (const float*)d_in[14];
    const float* mlp_w2     = (const float*)d_in[15];
    const float* mlp_b2     = (const float*)d_in[16];
    float* out = (float*)d_out;

    static float *p_h1 = 0, *p_zx = 0, *p_xbc = 0, *p_dt = 0, *p_y = 0;
    static float *p_yn = 0, *p_x2 = 0, *p_h2 = 0, *p_gl = 0;
    if (p_h1 == 0) {
        cudaGetSymbolAddress((void**)&p_h1,  g_h1);
        cudaGetSymbolAddress((void**)&p_zx,  g_zx);
        cudaGetSymbolAddress((void**)&p_xbc, g_xbc);
        cudaGetSymbolAddress((void**)&p_dt,  g_dt);
        cudaGetSymbolAddress((void**)&p_y,   g_y);
        cudaGetSymbolAddress((void**)&p_yn,  g_yn);
        cudaGetSymbolAddress((void**)&p_x2,  g_x2);
        cudaGetSymbolAddress((void**)&p_h2,  g_h2);
        cudaGetSymbolAddress((void**)&p_gl,  g_gl);
        cudaFuncSetAttribute(mm_kernel, cudaFuncAttributeMaxDynamicSharedMemorySize,
                             (int)SMEM_MM);
    }

    dim3 blk256(256, 1, 1);

    // 1) LN1
    ln_kernel<<<TT, 256>>>(x, ln1_w, ln1_b, p_h1);

    // 2) in_proj
    dim3 g1((DPROJ + 127) / 128, TT / 128, 1);
    mm_kernel<<<g1, blk256, SMEM_MM>>>(p_h1, in_proj_w, (const float*)0, (const float*)0,
                                       p_zx, TT, DPROJ, DM, 0);

    // 3) conv + dt
    conv_kernel<<<(TT * CONVD + 255) / 256, 256>>>(p_zx, conv_w, conv_b, p_xbc);
    dt_kernel<<<(TT * NH + 255) / 256, 256>>>(p_zx, dt_bias, p_dt);

    // 4) scan
    scan_kernel<<<B_ * NH * 2, 128>>>(p_xbc, p_dt, A_log, Dv, p_y);

    // 5) gated rmsnorm
    rmsnorm_kernel<<<TT, 256>>>(p_y, p_zx, norm_w, p_yn);

    // 6) out_proj + residual
    dim3 g2(DM / 128, TT / 128, 1);
    mm_kernel<<<g2, blk256, SMEM_MM>>>(p_yn, out_proj_w, (const float*)0, x,
                                       p_x2, TT, DM, DI, 1);

    // 7) LN2
    ln_kernel<<<TT, 256>>>(p_x2, ln2_w, ln2_b, p_h2);

    // 8) mlp1 + bias + gelu
    dim3 g3(4 * DM / 128, TT / 128, 1);
    mm_kernel<<<g3, blk256, SMEM_MM>>>(p_h2, mlp_w1, mlp_b1, (const float*)0,
                                       p_gl, TT, 4 * DM, DM, 2);

    // 9) mlp2 + bias + residual -> out
    dim3 g4(DM / 128, TT / 128, 1);
    mm_kernel<<<g4, blk256, SMEM_MM>>>(p_gl, mlp_w2, mlp_b2, p_x2,
                                       out, TT, DM, 4 * DM, 3);
}